// round 6
// baseline (speedup 1.0000x reference)
#include <cuda_runtime.h>
#include <cuda_bf16.h>

// VolumeSDF renderer: one warp per ray, 4 samples per lane.
// out[n] = sum_s T_s * (1 - exp(-tau_s + eps)) * color[n,s,:]
//   density = ALPHA * LaplaceCDF(-sdf; BETA)
//   tau_s   = density_s * delta_s,  delta = diff(depth), last = 1e10
//   T_s     = exp(-inclusive_cumsum(tau)_s)   (inclusive, per reference)

#define RENDER_ALPHA 10.0f
#define INV_BETA     20.0f      // 1 / 0.05
#define RENDER_EPS   1e-10f
#define FAR_DELTA    1e10f

__global__ __launch_bounds__(256)
void volume_sdf_render_kernel(const float* __restrict__ sdf,
                              const float* __restrict__ color,
                              const float* __restrict__ depth,
                              float* __restrict__ out,
                              int N)
{
    const int gtid = blockIdx.x * blockDim.x + threadIdx.x;
    const int ray  = gtid >> 5;          // one warp per ray
    const int lane = threadIdx.x & 31;
    if (ray >= N) return;

    const int S = 128;
    const long long base = (long long)ray * S + lane * 4;

    // Coalesced vector loads: 4 consecutive samples per lane.
    const float4 s4 = *reinterpret_cast<const float4*>(sdf   + base);
    const float4 d4 = *reinterpret_cast<const float4*>(depth + base);

    // Deltas. depth[4l+4] lives in the next lane's d4.x.
    const float dnext = __shfl_down_sync(0xffffffffu, d4.x, 1);
    float del[4];
    del[0] = d4.y - d4.x;
    del[1] = d4.z - d4.y;
    del[2] = d4.w - d4.z;
    del[3] = (lane == 31) ? FAR_DELTA : (dnext - d4.w);

    const float sd[4] = {s4.x, s4.y, s4.z, s4.w};

    float tau[4], trans[4];
#pragma unroll
    for (int i = 0; i < 4; ++i) {
        // LaplaceCDF(-sdf, b): sdf > 0 -> 0.5*exp(-sdf/b); else 1 - 0.5*exp(sdf/b)
        const float x = sd[i];
        float dens;
        if (x > 0.0f) dens = RENDER_ALPHA * 0.5f * expf(-x * INV_BETA);
        else          dens = RENDER_ALPHA * (1.0f - 0.5f * expf(x * INV_BETA));
        tau[i]   = dens * del[i];
        trans[i] = 1.0f - expf(-tau[i] + RENDER_EPS);
    }

    // Per-lane inclusive cumsum of the 4 taus.
    const float c0 = tau[0];
    const float c1 = c0 + tau[1];
    const float c2 = c1 + tau[2];
    const float c3 = c2 + tau[3];

    // Warp inclusive scan of lane totals.
    float incl = c3;
#pragma unroll
    for (int off = 1; off < 32; off <<= 1) {
        const float v = __shfl_up_sync(0xffffffffu, incl, off);
        if (lane >= off) incl += v;
    }
    // Exclusive prefix = previous lane's inclusive value. Do NOT compute it as
    // (incl - c3): lane 31's c3 contains the 1e10 far-delta tau and the
    // subtraction catastrophically cancels, zeroing the prefix for samples
    // 124-126 (this was the R1/R2 rel_err=0.33 bug).
    float prefix = __shfl_up_sync(0xffffffffu, incl, 1);
    if (lane == 0) prefix = 0.0f;

    const float w0 = expf(-(prefix + c0)) * trans[0];
    const float w1 = expf(-(prefix + c1)) * trans[1];
    const float w2 = expf(-(prefix + c2)) * trans[2];
    const float w3 = expf(-(prefix + c3)) * trans[3];

    // Color: 12 consecutive floats per lane (48 B, 16B-aligned) -> 3x float4.
    const long long cbase = base * 3;
    const float4 ca = *reinterpret_cast<const float4*>(color + cbase);
    const float4 cb = *reinterpret_cast<const float4*>(color + cbase + 4);
    const float4 cc = *reinterpret_cast<const float4*>(color + cbase + 8);
    // sample0=(ca.x,ca.y,ca.z) sample1=(ca.w,cb.x,cb.y)
    // sample2=(cb.z,cb.w,cc.x) sample3=(cc.y,cc.z,cc.w)
    float r = w0 * ca.x + w1 * ca.w + w2 * cb.z + w3 * cc.y;
    float g = w0 * ca.y + w1 * cb.x + w2 * cb.w + w3 * cc.z;
    float b = w0 * ca.z + w1 * cb.y + w2 * cc.x + w3 * cc.w;

    // Warp reduction over lanes (samples).
#pragma unroll
    for (int off = 16; off > 0; off >>= 1) {
        r += __shfl_xor_sync(0xffffffffu, r, off);
        g += __shfl_xor_sync(0xffffffffu, g, off);
        b += __shfl_xor_sync(0xffffffffu, b, off);
    }

    if (lane == 0) {
        out[ray * 3 + 0] = r;
        out[ray * 3 + 1] = g;
        out[ray * 3 + 2] = b;
    }
}

extern "C" void kernel_launch(void* const* d_in, const int* in_sizes, int n_in,
                              void* d_out, int out_size)
{
    // Identify buffers defensively by size. color is [N,128,3] -> uniquely 3x
    // larger than sdf/depth ([N,128] each).
    int ic = 0;
    for (int i = 1; i < n_in; ++i)
        if (in_sizes[i] > in_sizes[ic]) ic = i;

    int ia, ib;  // the two equal-size buffers, in index order
    if (ic == 0)      { ia = 1; ib = 2; }
    else if (ic == 1) { ia = 0; ib = 2; }
    else              { ia = 0; ib = 1; }

    int is, id;  // sdf index, depth index
    if (ic == 0) {
        // color first => name-sorted metadata (color, depth_values, sdf)
        id = ia; is = ib;
    } else {
        // insertion order (sdf, color, depth_values) or (sdf, depth, color)
        is = ia; id = ib;
    }

    const float* sdf   = (const float*)d_in[is];
    const float* color = (const float*)d_in[ic];
    const float* depth = (const float*)d_in[id];
    float* out = (float*)d_out;

    const int N = out_size / 3;                   // 65536 rays
    const int threads = 256;                      // 8 warps = 8 rays / block
    const int blocks  = (N * 32 + threads - 1) / threads;
    volume_sdf_render_kernel<<<blocks, threads>>>(sdf, color, depth, out, N);
}

// round 7
// speedup vs baseline: 1.0748x; 1.0748x over previous
#include <cuda_runtime.h>
#include <cuda_bf16.h>

// VolumeSDF renderer: one warp per ray, 4 samples per lane.
// out[n] = sum_s T_s * (1 - exp(-tau_s + eps)) * color[n,s,:]
//   density = ALPHA * LaplaceCDF(-sdf; BETA)
//   tau_s   = density_s * delta_s,  delta = diff(depth), last = 1e10
//   T_s     = exp(-inclusive_cumsum(tau)_s)

#define RENDER_ALPHA 10.0f
#define INV_BETA     20.0f      // 1 / 0.05
#define RENDER_EPS   1e-10f
#define FAR_DELTA    1e10f

__global__ __launch_bounds__(256)
void volume_sdf_render_kernel(const float* __restrict__ sdf,
                              const float* __restrict__ color,
                              const float* __restrict__ depth,
                              float* __restrict__ out,
                              int N)
{
    const int gtid = blockIdx.x * blockDim.x + threadIdx.x;
    const int ray  = gtid >> 5;          // one warp per ray
    const int lane = threadIdx.x & 31;
    if (ray >= N) return;

    const int S = 128;
    const long long base  = (long long)ray * S + lane * 4;
    const long long cbase = base * 3;

    // ---- Front-batch ALL global loads (5x LDG.128, MLP=5) ----
    const float4 s4 = *reinterpret_cast<const float4*>(sdf   + base);
    const float4 d4 = *reinterpret_cast<const float4*>(depth + base);
    const float4 ca = *reinterpret_cast<const float4*>(color + cbase);
    const float4 cb = *reinterpret_cast<const float4*>(color + cbase + 4);
    const float4 cc = *reinterpret_cast<const float4*>(color + cbase + 8);

    // Deltas. depth[4l+4] lives in the next lane's d4.x.
    const float dnext = __shfl_down_sync(0xffffffffu, d4.x, 1);
    float del[4];
    del[0] = d4.y - d4.x;
    del[1] = d4.z - d4.y;
    del[2] = d4.w - d4.z;
    del[3] = (lane == 31) ? FAR_DELTA : (dnext - d4.w);

    const float sd[4] = {s4.x, s4.y, s4.z, s4.w};

    float tau[4], trans[4];
#pragma unroll
    for (int i = 0; i < 4; ++i) {
        // LaplaceCDF(-x, b), branchless: e = 0.5*exp(-|x|/b)
        //   x > 0  -> e ; x <= 0 -> 1 - e
        const float x = sd[i];
        const float e = 0.5f * __expf(-fabsf(x) * INV_BETA);
        const float cdf = (x > 0.0f) ? e : (1.0f - e);
        tau[i]   = (RENDER_ALPHA * cdf) * del[i];
        trans[i] = 1.0f - __expf(-tau[i] + RENDER_EPS);
    }

    // Per-lane inclusive cumsum of the 4 taus.
    const float c0 = tau[0];
    const float c1 = c0 + tau[1];
    const float c2 = c1 + tau[2];
    const float c3 = c2 + tau[3];

    // Warp inclusive scan of lane totals.
    float incl = c3;
#pragma unroll
    for (int off = 1; off < 32; off <<= 1) {
        const float v = __shfl_up_sync(0xffffffffu, incl, off);
        if (lane >= off) incl += v;
    }
    // Exclusive prefix = previous lane's inclusive value. Do NOT compute it as
    // (incl - c3): lane 31's c3 contains the 1e10 far-delta tau and the
    // subtraction catastrophically cancels (R1/R2 rel_err=0.33 bug).
    float prefix = __shfl_up_sync(0xffffffffu, incl, 1);
    if (lane == 0) prefix = 0.0f;

    const float w0 = __expf(-(prefix + c0)) * trans[0];
    const float w1 = __expf(-(prefix + c1)) * trans[1];
    const float w2 = __expf(-(prefix + c2)) * trans[2];
    const float w3 = __expf(-(prefix + c3)) * trans[3];

    // sample0=(ca.x,ca.y,ca.z) sample1=(ca.w,cb.x,cb.y)
    // sample2=(cb.z,cb.w,cc.x) sample3=(cc.y,cc.z,cc.w)
    float r = w0 * ca.x + w1 * ca.w + w2 * cb.z + w3 * cc.y;
    float g = w0 * ca.y + w1 * cb.x + w2 * cb.w + w3 * cc.z;
    float b = w0 * ca.z + w1 * cb.y + w2 * cc.x + w3 * cc.w;

    // Warp reduction over lanes (samples).
#pragma unroll
    for (int off = 16; off > 0; off >>= 1) {
        r += __shfl_xor_sync(0xffffffffu, r, off);
        g += __shfl_xor_sync(0xffffffffu, g, off);
        b += __shfl_xor_sync(0xffffffffu, b, off);
    }

    if (lane == 0) {
        out[ray * 3 + 0] = r;
        out[ray * 3 + 1] = g;
        out[ray * 3 + 2] = b;
    }
}

extern "C" void kernel_launch(void* const* d_in, const int* in_sizes, int n_in,
                              void* d_out, int out_size)
{
    // Identify buffers defensively by size. color is [N,128,3] -> uniquely 3x
    // larger than sdf/depth ([N,128] each).
    int ic = 0;
    for (int i = 1; i < n_in; ++i)
        if (in_sizes[i] > in_sizes[ic]) ic = i;

    int ia, ib;  // the two equal-size buffers, in index order
    if (ic == 0)      { ia = 1; ib = 2; }
    else if (ic == 1) { ia = 0; ib = 2; }
    else              { ia = 0; ib = 1; }

    int is, id;  // sdf index, depth index
    if (ic == 0) {
        // color first => name-sorted metadata (color, depth_values, sdf)
        id = ia; is = ib;
    } else {
        // insertion order (sdf, color, depth_values)
        is = ia; id = ib;
    }

    const float* sdf   = (const float*)d_in[is];
    const float* color = (const float*)d_in[ic];
    const float* depth = (const float*)d_in[id];
    float* out = (float*)d_out;

    const int N = out_size / 3;                   // 65536 rays
    const int threads = 256;                      // 8 warps = 8 rays / block
    const int blocks  = (N * 32 + threads - 1) / threads;
    volume_sdf_render_kernel<<<blocks, threads>>>(sdf, color, depth, out, N);
}